// round 15
// baseline (speedup 1.0000x reference)
#include <cuda_runtime.h>
#include <cuda_fp16.h>
#include <cstdint>

#define NTOK 16384
#define DDIM 1024
#define HDIM 2048
#define NEXP 16
#define CAP  2560
#define BM 128
#define BN 128
#define KC 64
#define A_ROWB 144                   // 64 halves + 8 pad, bytes
#define B_ROWB 272                   // 128 halves + 8 pad, bytes
#define A_BYTES (BM * A_ROWB)        // 18432
#define B_BYTES (KC * B_ROWB)        // 17408
#define BUF_BYTES (A_BYTES + B_BYTES)
#define NSTAGE 3
#define SMEM_BYTES (NSTAGE * BUF_BYTES)  // 107520 -> 2 CTAs/SM

// ---------------- scratch (device globals; no allocation) ----------------
__device__ __half g_act  [(size_t)NEXP * CAP * HDIM];       // shared-phase act [NTOK][2H]
__device__ __half g_act2 [(size_t)NEXP * CAP * HDIM];       // routed act [e][CAP][H]
__device__ __half g_y    [(size_t)NEXP * CAP * DDIM];       // routed y staging
__device__ __half g_hx   [(size_t)NTOK * DDIM];
__device__ __half g_wg   [(size_t)NEXP * DDIM * 2 * HDIM];  // interleaved w1/w3
__device__ __half g_swg  [(size_t)2 * DDIM * 2 * HDIM];     // interleaved sw1/sw3
__device__ __half g_w2h  [(size_t)NEXP * HDIM * DDIM];
__device__ __half g_sw2h [(size_t)2 * HDIM * DDIM];
__device__ int    g_topi[NTOK * 2];
__device__ float  g_wts [NTOK * 2];
__device__ int    g_tokl[NEXP * NTOK];
__device__ float  g_wl  [NEXP * NTOK];
__device__ int    g_ktok[NEXP * CAP];
__device__ float  g_kw  [NEXP * CAP];
__device__ int    g_mk  [NEXP];
__device__ int    g_pos [NTOK * 2];

// prep-work argument bundle (passed by value to the fat GEMM1 launch)
struct PrepArgs {
    const float *x, *gw, *gb, *ew1, *ew3, *ew2, *sw2;
    __half *wg, *w2h, *sw2h;
    int *topi;
    float *wts;
};

// ---------------- helpers ----------------
__device__ __forceinline__ void cpasync16(uint32_t dst, const void* src, int srcsz) {
    asm volatile("cp.async.cg.shared.global [%0], [%1], 16, %2;"
                 :: "r"(dst), "l"(src), "r"(srcsz));
}
#define CP_COMMIT() asm volatile("cp.async.commit_group;" ::: "memory")

// ---------------- prep device helpers ----------------
__device__ __forceinline__ void dev_interleave(const float* w1, const float* w3,
                                               __half* wg, int n4, int start, int stride) {
    for (int i = start; i < n4; i += stride) {
        float4 a = reinterpret_cast<const float4*>(w1)[i];
        float4 b = reinterpret_cast<const float4*>(w3)[i];
        __half2 h0 = __floats2half2_rn(a.x, b.x);
        __half2 h1 = __floats2half2_rn(a.y, b.y);
        __half2 h2 = __floats2half2_rn(a.z, b.z);
        __half2 h3 = __floats2half2_rn(a.w, b.w);
        uint4 o;
        o.x = *reinterpret_cast<uint32_t*>(&h0);
        o.y = *reinterpret_cast<uint32_t*>(&h1);
        o.z = *reinterpret_cast<uint32_t*>(&h2);
        o.w = *reinterpret_cast<uint32_t*>(&h3);
        reinterpret_cast<uint4*>(wg)[i] = o;
    }
}

__device__ __forceinline__ void dev_tohalf(const float* s, __half* o, int n4,
                                           int start, int stride) {
    for (int i = start; i < n4; i += stride) {
        float4 v = reinterpret_cast<const float4*>(s)[i];
        __half2* o2 = reinterpret_cast<__half2*>(o);
        o2[i * 2 + 0] = __floats2half2_rn(v.x, v.y);
        o2[i * 2 + 1] = __floats2half2_rn(v.z, v.w);
    }
}

__device__ __forceinline__ void dev_gate(const PrepArgs& pa, int p) {
    int t = p * 8 + (threadIdx.x >> 5);
    int lane = threadIdx.x & 31;
    if (t >= NTOK) return;
    const float* xr = pa.x + (size_t)t * DDIM;
    float s[NEXP];
#pragma unroll
    for (int e = 0; e < NEXP; e++) s[e] = 0.f;
    for (int i = lane; i < DDIM; i += 32) {
        float xv = xr[i];
        const float4* w4 = reinterpret_cast<const float4*>(pa.gw + (size_t)i * NEXP);
#pragma unroll
        for (int q = 0; q < 4; q++) {
            float4 w = w4[q];
            s[q*4+0] += xv * w.x; s[q*4+1] += xv * w.y;
            s[q*4+2] += xv * w.z; s[q*4+3] += xv * w.w;
        }
    }
#pragma unroll
    for (int e = 0; e < NEXP; e++)
#pragma unroll
        for (int off = 16; off > 0; off >>= 1)
            s[e] += __shfl_xor_sync(0xffffffffu, s[e], off);
    if (lane == 0) {
        float mx = s[0];
#pragma unroll
        for (int e = 1; e < NEXP; e++) mx = fmaxf(mx, s[e]);
        float sum = 0.f, sc[NEXP];
#pragma unroll
        for (int e = 0; e < NEXP; e++) { sc[e] = expf(s[e] - mx); sum += sc[e]; }
        float inv = 1.f / sum;
#pragma unroll
        for (int e = 0; e < NEXP; e++) sc[e] = sc[e] * inv + pa.gb[e];
        int i0 = 0; float v0 = sc[0];
#pragma unroll
        for (int e = 1; e < NEXP; e++) if (sc[e] > v0) { v0 = sc[e]; i0 = e; }
        int i1 = 0; float v1 = -1e30f;
#pragma unroll
        for (int e = 0; e < NEXP; e++) if (e != i0 && sc[e] > v1) { v1 = sc[e]; i1 = e; }
        pa.topi[t*2+0] = i0; pa.topi[t*2+1] = i1;
        pa.wts [t*2+0] = s[i0]; pa.wts[t*2+1] = s[i1];
    }
}

__device__ __forceinline__ void prep_dispatch(const PrepArgs& pa) {
    int p = blockIdx.y * gridDim.x + blockIdx.x;
    int tid = threadIdx.x;
    if (p < 2048) {                       // gate: 8 tokens per block
        dev_gate(pa, p);
    } else if (p < 2560) {                // interleave ew1/ew3 -> wg
        int bid = p - 2048;
        dev_interleave(pa.ew1, pa.ew3, pa.wg, NEXP*DDIM*HDIM/4,
                       bid * 256 + tid, 512 * 256);
    } else if (p < 2816) {                // tohalf ew2 -> w2h
        int bid = p - 2560;
        dev_tohalf(pa.ew2, pa.w2h, NEXP*HDIM*DDIM/4, bid * 256 + tid, 256 * 256);
    } else if (p < 2848) {                // tohalf sw2 -> sw2h
        int bid = p - 2816;
        dev_tohalf(pa.sw2, pa.sw2h, 2*HDIM*DDIM/4, bid * 256 + tid, 32 * 256);
    }
}

// ---------------- consolidated front-end prep (one launch) ----------------
__global__ void prep0_kernel(const float* __restrict__ x, __half* __restrict__ hx,
                             const float* __restrict__ sw1, const float* __restrict__ sw3,
                             __half* __restrict__ swg,
                             int* __restrict__ pos, int* __restrict__ mk) {
    int p = blockIdx.x;
    int tid = threadIdx.x;
    if (p < 16384) {
        int i = p * 256 + tid;
        dev_tohalf(x, hx, NTOK * DDIM / 4, i, 1 << 30);
    } else if (p < 20480) {
        int i = (p - 16384) * 256 + tid;
        dev_interleave(sw1, sw3, swg, 2 * DDIM * HDIM / 4, i, 1 << 30);
    } else if (p < 20512) {
        int i = (p - 20480) * 256 + tid;
        if (i < NTOK * 2) pos[i] = -1;
    } else {
        if (tid < NEXP) mk[tid] = 0;
    }
}

__device__ __forceinline__ unsigned fkey(float f) {
    unsigned u = __float_as_uint(f);
    return (u & 0x80000000u) ? ~u : (u | 0x80000000u);
}

// ---------------- merged assign+select: one block per expert ----------------
__global__ void assign_select_kernel(const int* __restrict__ topi,
                                     const float* __restrict__ wts,
                                     int* __restrict__ tokl, float* __restrict__ wl,
                                     int* __restrict__ ktok, float* __restrict__ kw,
                                     int* __restrict__ mk, int* __restrict__ pos) {
    int e = blockIdx.x;
    int tid = threadIdx.x;
    int* tl = tokl + (size_t)e * NTOK;
    float* wv = wl + (size_t)e * NTOK;

    __shared__ int hist[256];
    __shared__ int eq_tok[2048];
    __shared__ int eq_src[2048];
    __shared__ int s_n, s_pfx, s_rem, s_nk, s_neq;

    // phase A: scan topi, build this expert's membership list
    if (tid == 0) s_n = 0;
    __syncthreads();
    for (int i = tid; i < NTOK * 2; i += blockDim.x) {
        if (topi[i] == e) {
            int p = atomicAdd(&s_n, 1);
            tl[p] = i >> 1;
            wv[p] = wts[i];
        }
    }
    __syncthreads();
    int n = s_n;

    if (n <= CAP) {
        for (int i = tid; i < n; i += blockDim.x) {
            int tkn = tl[i];
            ktok[(size_t)e * CAP + i] = tkn;
            kw  [(size_t)e * CAP + i] = wv[i];
            int which = (topi[tkn * 2] == e) ? 0 : 1;
            pos[tkn * 2 + which] = e * CAP + i;
        }
        if (tid == 0) mk[e] = n;
        return;
    }

    // phase B: radix-select threshold
    if (tid == 0) { s_pfx = 0; s_rem = CAP; }
    __syncthreads();
    for (int shift = 24; shift >= 0; shift -= 8) {
        for (int b = tid; b < 256; b += blockDim.x) hist[b] = 0;
        __syncthreads();
        unsigned pfx = (unsigned)s_pfx;
        for (int i = tid; i < n; i += blockDim.x) {
            unsigned key = fkey(wv[i]);
            if (shift == 24 || (key >> (shift + 8)) == pfx)
                atomicAdd(&hist[(key >> shift) & 255], 1);
        }
        __syncthreads();
        if (tid == 0) {
            int rem = s_rem;
            int b = 255;
            for (; b > 0; b--) { if (hist[b] >= rem) break; rem -= hist[b]; }
            s_pfx = (int)((pfx << 8) | (unsigned)b);
            s_rem = rem;
        }
        __syncthreads();
    }
    unsigned T = (unsigned)s_pfx;
    int rem = s_rem;
    if (tid == 0) { s_nk = 0; s_neq = 0; }
    __syncthreads();
    for (int i = tid; i < n; i += blockDim.x) {
        unsigned key = fkey(wv[i]);
        if (key > T) {
            int p = atomicAdd(&s_nk, 1);
            int tkn = tl[i];
            ktok[(size_t)e * CAP + p] = tkn;
            kw  [(size_t)e * CAP + p] = wv[i];
            int which = (topi[tkn * 2] == e) ? 0 : 1;
            pos[tkn * 2 + which] = e * CAP + p;
        } else if (key == T) {
            int p = atomicAdd(&s_neq, 1);
            if (p < 2048) { eq_tok[p] = tl[i]; eq_src[p] = i; }
        }
    }
    __syncthreads();
    int neq = min(s_neq, 2048);
    for (int j = tid; j < neq; j += blockDim.x) {
        int tj = eq_tok[j];
        int rank = 0;
        for (int l = 0; l < neq; l++) rank += (eq_tok[l] < tj);
        if (rank < rem) {
            int p = atomicAdd(&s_nk, 1);
            ktok[(size_t)e * CAP + p] = tj;
            kw  [(size_t)e * CAP + p] = wv[eq_src[j]];
            int which = (topi[tj * 2] == e) ? 0 : 1;
            pos[tj * 2 + which] = e * CAP + p;
        }
    }
    __syncthreads();
    if (tid == 0) mk[e] = s_nk;
}

// ---------------- shared GEMM core: C = A[M,K] @ B[K,N] ----------------
// CTA tile 128x128, 8 warps (2m x 4n, warp tile 64x32), KC=64,
// 3-stage cp.async pipeline, fp32 accumulators. Caller pre-offsets A/B/Cv/gl/rw by z.
// MODE 2: C(float)[r][c] = acc*scale
// MODE 3: C(half) [r][c] = acc*rw[r]*scale
// MODE 5: fused SwiGLU: B interleaved (w1|w3); C(half)[r][c/2] = silu(v0)*v1
template<int MODE, bool GATHER>
__device__ __forceinline__ void gemm_core(
    const __half* __restrict__ A, int lda,
    const __half* __restrict__ B,
    void* __restrict__ Cv, int ldc,
    int M, int N, int K,
    const int* __restrict__ gl, const float* __restrict__ rw,
    float outscale, int row0, int col0, char* smem)
{
    __half* Ch = (__half*)Cv;
    float*  Cf = (float*)Cv;

    int tid = threadIdx.x;
    int lane = tid & 31, wid = tid >> 5;
    int wm = wid >> 2, wn = wid & 3;
    int g = lane >> 2, t4 = lane & 3;

    int arow = tid >> 1, aseg = tid & 1;
    const __half* aptr = A;
    int asz = 0;
    {
        int r = row0 + arow;
        if (r < M) {
            int gr = GATHER ? gl[r] : r;
            aptr = A + (size_t)gr * lda + aseg * 32;
            asz = 16;
        }
    }
    int bkrow = tid >> 2, bseg = tid & 3;
    const __half* bptr = B + (size_t)bkrow * N + col0 + bseg * 32;
    uint32_t sbase = (uint32_t)__cvta_generic_to_shared(smem);
    uint32_t aoff = (uint32_t)arow * A_ROWB + (uint32_t)aseg * 64;
    uint32_t boff = (uint32_t)A_BYTES + (uint32_t)bkrow * B_ROWB + (uint32_t)bseg * 64;

    uint32_t a_lm = (uint32_t)(wm * 64 + (lane & 15)) * A_ROWB + (uint32_t)(lane >> 4) * 16;
    uint32_t b_lm = (uint32_t)A_BYTES
                  + (uint32_t)((((lane >> 3) & 1) * 8 + (lane & 7))) * B_ROWB
                  + (uint32_t)(wn * 32 + (lane >> 4) * 8) * 2;

    float acc[4][4][4];
#pragma unroll
    for (int mt = 0; mt < 4; mt++)
#pragma unroll
        for (int nt = 0; nt < 4; nt++)
#pragma unroll
            for (int q = 0; q < 4; q++) acc[mt][nt][q] = 0.f;

    int nk = K / KC;

#define ISSUE_STAGE(KB) do { \
    uint32_t bs_ = (uint32_t)((KB) % NSTAGE) * BUF_BYTES; \
    const __half* as_ = aptr + (KB) * KC; \
    const __half* bs2_ = bptr + (size_t)(KB) * KC * N; \
    uint32_t dA_ = sbase + bs_ + aoff; \
    uint32_t dB_ = sbase + bs_ + boff; \
    _Pragma("unroll") \
    for (int c_ = 0; c_ < 4; c_++) cpasync16(dA_ + c_ * 16, as_ + c_ * 8, asz); \
    _Pragma("unroll") \
    for (int c_ = 0; c_ < 4; c_++) cpasync16(dB_ + c_ * 16, bs2_ + c_ * 8, 16); \
} while (0)

    ISSUE_STAGE(0); CP_COMMIT();
    ISSUE_STAGE(1); CP_COMMIT();

#pragma unroll 1
    for (int kb = 0; kb < nk; kb++) {
        asm volatile("cp.async.wait_group 1;" ::: "memory");
        __syncthreads();
        if (kb + 2 < nk) ISSUE_STAGE(kb + 2);
        CP_COMMIT();

        uint32_t bufb = sbase + (uint32_t)(kb % NSTAGE) * BUF_BYTES;
#pragma unroll
        for (int ks = 0; ks < 4; ks++) {
            uint32_t af[4][4], bf[4][2];
#pragma unroll
            for (int mt = 0; mt < 4; mt++) {
                uint32_t ad = bufb + a_lm + (uint32_t)mt * (16 * A_ROWB) + (uint32_t)ks * 32;
                asm volatile("ldmatrix.sync.aligned.m8n8.x4.shared.b16 {%0,%1,%2,%3}, [%4];"
                             : "=r"(af[mt][0]), "=r"(af[mt][1]), "=r"(af[mt][2]), "=r"(af[mt][3])
                             : "r"(ad));
            }
#pragma unroll
            for (int p = 0; p < 2; p++) {
                uint32_t bd = bufb + b_lm + (uint32_t)ks * (16 * B_ROWB) + (uint32_t)p * 32;
                asm volatile("ldmatrix.sync.aligned.m8n8.x4.trans.shared.b16 {%0,%1,%2,%3}, [%4];"
                             : "=r"(bf[2*p][0]), "=r"(bf[2*p][1]),
                               "=r"(bf[2*p+1][0]), "=r"(bf[2*p+1][1])
                             : "r"(bd));
            }
#pragma unroll
            for (int mt = 0; mt < 4; mt++)
#pragma unroll
                for (int nt = 0; nt < 4; nt++)
                    asm volatile(
                        "mma.sync.aligned.m16n8k16.row.col.f32.f16.f16.f32 "
                        "{%0,%1,%2,%3}, {%4,%5,%6,%7}, {%8,%9}, {%0,%1,%2,%3};"
                        : "+f"(acc[mt][nt][0]), "+f"(acc[mt][nt][1]),
                          "+f"(acc[mt][nt][2]), "+f"(acc[mt][nt][3])
                        : "r"(af[mt][0]), "r"(af[mt][1]), "r"(af[mt][2]), "r"(af[mt][3]),
                          "r"(bf[nt][0]), "r"(bf[nt][1]));
        }
    }
#undef ISSUE_STAGE

    // epilogue
#pragma unroll
    for (int mt = 0; mt < 4; mt++) {
#pragma unroll
        for (int h = 0; h < 2; h++) {
            int rr = row0 + wm * 64 + mt * 16 + g + h * 8;
            if (rr >= M) continue;
            float scl = outscale;
            if (MODE == 3) scl = rw[rr] * outscale;
#pragma unroll
            for (int nt = 0; nt < 4; nt++) {
                int cc = col0 + wn * 32 + nt * 8 + t4 * 2;
                float v0 = acc[mt][nt][h * 2 + 0];
                float v1 = acc[mt][nt][h * 2 + 1];
                if (MODE == 2) {
                    size_t off = (size_t)rr * ldc + cc;
                    *reinterpret_cast<float2*>(Cf + off) =
                        make_float2(v0 * outscale, v1 * outscale);
                } else if (MODE == 3) {
                    size_t off = (size_t)rr * ldc + cc;
                    *reinterpret_cast<__half2*>(Ch + off) =
                        __floats2half2_rn(v0 * scl, v1 * scl);
                } else { // MODE 5
                    float sv = v0 / (1.f + __expf(-v0)) * v1;
                    Ch[(size_t)rr * ldc + (cc >> 1)] = __float2half_rn(sv);
                }
            }
        }
    }
}

// ---------------- GEMM wrapper (GEMM1 fat w/ prep slice; GEMM4) ----------------
template<int MODE, bool GATHER, bool PREP>
__global__ void __launch_bounds__(256, 2)
gemm_h(const __half* __restrict__ A, size_t sAz, int lda,
       const __half* __restrict__ B, size_t sBz,
       void* __restrict__ Cv, size_t sCz, int ldc,
       const int* __restrict__ mlist, int Mmax, int N, int K,
       const int* __restrict__ gidx, const float* __restrict__ roww,
       float outscale, int Zmain, PrepArgs pa)
{
    extern __shared__ char smem[];
    if (PREP && blockIdx.z == (unsigned)Zmain) {
        prep_dispatch(pa);
        return;
    }
    int z = blockIdx.z;
    int M = mlist ? mlist[z] : Mmax;
    int row0 = blockIdx.y * BM;
    if (row0 >= M) return;
    int col0 = blockIdx.x * BN;

    const int*   gl = gidx ? gidx + (size_t)z * CAP : nullptr;
    const float* rw = roww ? roww + (size_t)z * CAP : nullptr;
    void* Cz = (MODE == 2) ? Cv : (void*)((__half*)Cv + sCz * z);

    gemm_core<MODE, GATHER>(A + sAz * z, lda, B + sBz * z, Cz, ldc,
                            M, N, K, gl, rw, outscale, row0, col0, smem);
}

// ---------------- fused middle launch: shared-down (z=0,1) + routed-up (z=2..17) ----
__global__ void __launch_bounds__(256, 2)
gemm_dual(const __half* __restrict__ hx, const __half* __restrict__ wg,
          __half* __restrict__ act2, const int* __restrict__ mk,
          const int* __restrict__ ktok,
          const __half* __restrict__ actS, const __half* __restrict__ sw2h,
          float* __restrict__ out)
{
    extern __shared__ char smem[];
    if (blockIdx.z < 2) {
        // shared-down: C(float) = act[NTOK][2H] @ sw2h[2H][D] * 0.5 ; 1024 tiles (8 x 128)
        int p = blockIdx.z * 640 + blockIdx.y * 32 + blockIdx.x;
        if (p >= (DDIM / BN) * (NTOK / BM)) return;
        int by = p >> 3, bx = p & 7;
        gemm_core<2, false>(actS, 2 * HDIM, sw2h, out, DDIM,
                            NTOK, DDIM, 2 * HDIM, nullptr, nullptr,
                            0.5f, by * BM, bx * BN, smem);
    } else {
        // routed-up fused SwiGLU: act2[e] = swiglu-mix(hx[ktok] @ wg[e])
        int z = blockIdx.z - 2;
        int M = mk[z];
        int row0 = blockIdx.y * BM;
        if (row0 >= M) return;
        gemm_core<5, true>(hx, DDIM, wg + (size_t)z * DDIM * 2 * HDIM,
                           act2 + (size_t)z * CAP * HDIM, HDIM,
                           M, 2 * HDIM, DDIM, ktok + (size_t)z * CAP, nullptr,
                           1.f, row0, blockIdx.x * BN, smem);
    }
}

// ---------------- final combine: out[t] += y[pos0] + y[pos1] ----------------
__global__ void combine_kernel(const int* __restrict__ pos, const __half* __restrict__ y,
                               float* __restrict__ out) {
    int i = blockIdx.x * blockDim.x + threadIdx.x;
    int tok = i >> 8;
    int c = (i & 255) * 4;
    int p0 = pos[tok * 2], p1 = pos[tok * 2 + 1];
    float4 o = *reinterpret_cast<float4*>(out + (size_t)tok * DDIM + c);
    if (p0 >= 0) {
        __half2 a = *reinterpret_cast<const __half2*>(y + (size_t)p0 * DDIM + c);
        __half2 b = *reinterpret_cast<const __half2*>(y + (size_t)p0 * DDIM + c + 2);
        o.x += __low2float(a); o.y += __high2float(a);
        o.z += __low2float(b); o.w += __high2float(b);
    }
    if (p1 >= 0) {
        __half2 a = *reinterpret_cast<const __half2*>(y + (size_t)p1 * DDIM + c);
        __half2 b = *reinterpret_cast<const __half2*>(y + (size_t)p1 * DDIM + c + 2);
        o.x += __low2float(a); o.y += __high2float(a);
        o.z += __low2float(b); o.w += __high2float(b);
    }
    *reinterpret_cast<float4*>(out + (size_t)tok * DDIM + c) = o;
}

// ---------------- host launcher ----------------
extern "C" void kernel_launch(void* const* d_in, const int* in_sizes, int n_in,
                              void* d_out, int out_size) {
    const float* x   = (const float*)d_in[0];
    const float* gw  = (const float*)d_in[1];
    const float* gb  = (const float*)d_in[2];
    const float* ew1 = (const float*)d_in[3];
    const float* ew3 = (const float*)d_in[4];
    const float* ew2 = (const float*)d_in[5];
    const float* sw1 = (const float*)d_in[6];
    const float* sw3 = (const float*)d_in[7];
    const float* sw2 = (const float*)d_in[8];
    float* out = (float*)d_out;

    __half *act, *act2, *yb, *hx, *wg, *swg, *w2h, *sw2h;
    float *wts, *wl, *kw;
    int *topi, *tokl, *ktok, *mk, *pos;
    cudaGetSymbolAddress((void**)&act,  g_act);
    cudaGetSymbolAddress((void**)&act2, g_act2);
    cudaGetSymbolAddress((void**)&yb,   g_y);
    cudaGetSymbolAddress((void**)&hx,   g_hx);
    cudaGetSymbolAddress((void**)&wg,   g_wg);
    cudaGetSymbolAddress((void**)&swg,  g_swg);
    cudaGetSymbolAddress((void**)&w2h,  g_w2h);
    cudaGetSymbolAddress((void**)&sw2h, g_sw2h);
    cudaGetSymbolAddress((void**)&topi, g_topi);
    cudaGetSymbolAddress((void**)&wts,  g_wts);
    cudaGetSymbolAddress((void**)&tokl, g_tokl);
    cudaGetSymbolAddress((void**)&wl,   g_wl);
    cudaGetSymbolAddress((void**)&ktok, g_ktok);
    cudaGetSymbolAddress((void**)&kw,   g_kw);
    cudaGetSymbolAddress((void**)&mk,   g_mk);
    cudaGetSymbolAddress((void**)&pos,  g_pos);

    PrepArgs pa;
    pa.x = x; pa.gw = gw; pa.gb = gb;
    pa.ew1 = ew1; pa.ew3 = ew3; pa.ew2 = ew2; pa.sw2 = sw2;
    pa.wg = wg; pa.w2h = w2h; pa.sw2h = sw2h;
    pa.topi = topi; pa.wts = wts;
    PrepArgs pz = {};

    cudaFuncSetAttribute((const void*)gemm_h<5,false,true>,  cudaFuncAttributeMaxDynamicSharedMemorySize, SMEM_BYTES);
    cudaFuncSetAttribute((const void*)gemm_h<3,false,false>, cudaFuncAttributeMaxDynamicSharedMemorySize, SMEM_BYTES);
    cudaFuncSetAttribute((const void*)gemm_dual,             cudaFuncAttributeMaxDynamicSharedMemorySize, SMEM_BYTES);

    // 0: consolidated front-end (hx convert, swg interleave, pos/mk init)
    prep0_kernel<<<20513, 256>>>(x, hx, sw1, sw3, swg, pos, mk);

    // 1: FAT shared fused-up GEMM (z=0,1) + prep slice (z=2): gate, interleave wg,
    //    tohalf w2h, tohalf sw2h — hidden under tensor-bound GEMM work.
    gemm_h<5,false,true><<<dim3(2*HDIM/BN, NTOK/BM, 3), 256, SMEM_BYTES>>>(
        hx, 0, DDIM, swg, (size_t)DDIM*2*HDIM, act, (size_t)HDIM, 2*HDIM,
        nullptr, NTOK, 2*HDIM, DDIM, nullptr, nullptr, 1.f, 2, pa);

    // 2: merged assign+select (one launch, 16 blocks; per-expert scan of topi)
    assign_select_kernel<<<NEXP, 256>>>(topi, wts, tokl, wl, ktok, kw, mk, pos);

    // 3: FUSED middle launch — shared-down (long-K tiles first, z=0,1) + routed-up
    gemm_dual<<<dim3(2*HDIM/BN, CAP/BM, NEXP + 2), 256, SMEM_BYTES>>>(
        hx, wg, act2, mk, ktok, act, sw2h, out);

    // 4: routed down-proj into y staging
    gemm_h<3,false,false><<<dim3(DDIM/BN, CAP/BM, NEXP), 256, SMEM_BYTES>>>(
        act2, (size_t)CAP*HDIM, HDIM, w2h, (size_t)HDIM*DDIM, yb, (size_t)CAP*DDIM, DDIM,
        mk, CAP, DDIM, HDIM, nullptr, kw, 1.f, -1, pz);

    // 5: final gather-sum (no atomics)
    combine_kernel<<<NTOK * 256 / 256, 256>>>(pos, yb, out);
}

// round 16
// speedup vs baseline: 1.0091x; 1.0091x over previous
#include <cuda_runtime.h>
#include <cuda_fp16.h>
#include <cstdint>

#define NTOK 16384
#define DDIM 1024
#define HDIM 2048
#define NEXP 16
#define CAP  2560
#define BM 128
#define BN 128
#define KC 64
#define A_ROWB 144                   // 64 halves + 8 pad, bytes
#define B_ROWB 272                   // 128 halves + 8 pad, bytes
#define A_BYTES (BM * A_ROWB)        // 18432
#define B_BYTES (KC * B_ROWB)        // 17408
#define BUF_BYTES (A_BYTES + B_BYTES)
#define NSTAGE 3
#define SMEM_BYTES (NSTAGE * BUF_BYTES)  // 107520 -> 2 CTAs/SM

// ---------------- scratch (device globals; no allocation) ----------------
__device__ __half g_act  [(size_t)NEXP * CAP * HDIM];       // shared-phase act [NTOK][2H]
__device__ __half g_act2 [(size_t)NEXP * CAP * HDIM];       // routed act [e][CAP][H]
__device__ __half g_y    [(size_t)NEXP * CAP * DDIM];       // routed y staging
__device__ __half g_hx   [(size_t)NTOK * DDIM];
__device__ __half g_wg   [(size_t)NEXP * DDIM * 2 * HDIM];  // interleaved w1/w3
__device__ __half g_swg  [(size_t)2 * DDIM * 2 * HDIM];     // interleaved sw1/sw3
__device__ __half g_w2h  [(size_t)NEXP * HDIM * DDIM];
__device__ __half g_sw2h [(size_t)2 * HDIM * DDIM];
__device__ int    g_topi[NTOK * 2];
__device__ float  g_wts [NTOK * 2];
__device__ int    g_cnt [NEXP];
__device__ int    g_tokl[NEXP * NTOK];
__device__ float  g_wl  [NEXP * NTOK];
__device__ int    g_ktok[NEXP * CAP];
__device__ float  g_kw  [NEXP * CAP];
__device__ int    g_mk  [NEXP];
__device__ int    g_pos [NTOK * 2];

// prep-work argument bundle (passed by value to the fat GEMM1 launch)
struct PrepArgs {
    const float *x, *gw, *gb, *ew1, *ew3, *ew2, *sw2;
    __half *wg, *w2h, *sw2h;
    int *topi;
    float *wts;
};

// ---------------- helpers ----------------
__device__ __forceinline__ void cpasync16(uint32_t dst, const void* src, int srcsz) {
    asm volatile("cp.async.cg.shared.global [%0], [%1], 16, %2;"
                 :: "r"(dst), "l"(src), "r"(srcsz));
}
#define CP_COMMIT() asm volatile("cp.async.commit_group;" ::: "memory")

// ---------------- prep device helpers ----------------
__device__ __forceinline__ void dev_interleave(const float* w1, const float* w3,
                                               __half* wg, int n4, int start, int stride) {
    for (int i = start; i < n4; i += stride) {
        float4 a = reinterpret_cast<const float4*>(w1)[i];
        float4 b = reinterpret_cast<const float4*>(w3)[i];
        __half2 h0 = __floats2half2_rn(a.x, b.x);
        __half2 h1 = __floats2half2_rn(a.y, b.y);
        __half2 h2 = __floats2half2_rn(a.z, b.z);
        __half2 h3 = __floats2half2_rn(a.w, b.w);
        uint4 o;
        o.x = *reinterpret_cast<uint32_t*>(&h0);
        o.y = *reinterpret_cast<uint32_t*>(&h1);
        o.z = *reinterpret_cast<uint32_t*>(&h2);
        o.w = *reinterpret_cast<uint32_t*>(&h3);
        reinterpret_cast<uint4*>(wg)[i] = o;
    }
}

__device__ __forceinline__ void dev_tohalf(const float* s, __half* o, int n4,
                                           int start, int stride) {
    for (int i = start; i < n4; i += stride) {
        float4 v = reinterpret_cast<const float4*>(s)[i];
        __half2* o2 = reinterpret_cast<__half2*>(o);
        o2[i * 2 + 0] = __floats2half2_rn(v.x, v.y);
        o2[i * 2 + 1] = __floats2half2_rn(v.z, v.w);
    }
}

__device__ __forceinline__ void dev_gate(const PrepArgs& pa, int p) {
    int t = p * 8 + (threadIdx.x >> 5);
    int lane = threadIdx.x & 31;
    if (t >= NTOK) return;
    const float* xr = pa.x + (size_t)t * DDIM;
    float s[NEXP];
#pragma unroll
    for (int e = 0; e < NEXP; e++) s[e] = 0.f;
    for (int i = lane; i < DDIM; i += 32) {
        float xv = xr[i];
        const float4* w4 = reinterpret_cast<const float4*>(pa.gw + (size_t)i * NEXP);
#pragma unroll
        for (int q = 0; q < 4; q++) {
            float4 w = w4[q];
            s[q*4+0] += xv * w.x; s[q*4+1] += xv * w.y;
            s[q*4+2] += xv * w.z; s[q*4+3] += xv * w.w;
        }
    }
#pragma unroll
    for (int e = 0; e < NEXP; e++)
#pragma unroll
        for (int off = 16; off > 0; off >>= 1)
            s[e] += __shfl_xor_sync(0xffffffffu, s[e], off);
    if (lane == 0) {
        float mx = s[0];
#pragma unroll
        for (int e = 1; e < NEXP; e++) mx = fmaxf(mx, s[e]);
        float sum = 0.f, sc[NEXP];
#pragma unroll
        for (int e = 0; e < NEXP; e++) { sc[e] = expf(s[e] - mx); sum += sc[e]; }
        float inv = 1.f / sum;
#pragma unroll
        for (int e = 0; e < NEXP; e++) sc[e] = sc[e] * inv + pa.gb[e];
        int i0 = 0; float v0 = sc[0];
#pragma unroll
        for (int e = 1; e < NEXP; e++) if (sc[e] > v0) { v0 = sc[e]; i0 = e; }
        int i1 = 0; float v1 = -1e30f;
#pragma unroll
        for (int e = 0; e < NEXP; e++) if (e != i0 && sc[e] > v1) { v1 = sc[e]; i1 = e; }
        pa.topi[t*2+0] = i0; pa.topi[t*2+1] = i1;
        pa.wts [t*2+0] = s[i0]; pa.wts[t*2+1] = s[i1];
    }
}

__device__ __forceinline__ void prep_dispatch(const PrepArgs& pa) {
    int p = blockIdx.y * gridDim.x + blockIdx.x;
    int tid = threadIdx.x;
    if (p < 2048) {                       // gate: 8 tokens per block
        dev_gate(pa, p);
    } else if (p < 2560) {                // interleave ew1/ew3 -> wg
        int bid = p - 2048;
        dev_interleave(pa.ew1, pa.ew3, pa.wg, NEXP*DDIM*HDIM/4,
                       bid * 256 + tid, 512 * 256);
    } else if (p < 2816) {                // tohalf ew2 -> w2h
        int bid = p - 2560;
        dev_tohalf(pa.ew2, pa.w2h, NEXP*HDIM*DDIM/4, bid * 256 + tid, 256 * 256);
    } else if (p < 2848) {                // tohalf sw2 -> sw2h
        int bid = p - 2816;
        dev_tohalf(pa.sw2, pa.sw2h, 2*HDIM*DDIM/4, bid * 256 + tid, 32 * 256);
    }
}

// ---------------- consolidated front-end prep (one launch) ----------------
__global__ void prep0_kernel(const float* __restrict__ x, __half* __restrict__ hx,
                             const float* __restrict__ sw1, const float* __restrict__ sw3,
                             __half* __restrict__ swg,
                             int* __restrict__ pos, int* __restrict__ cnt,
                             int* __restrict__ mk) {
    int p = blockIdx.x;
    int tid = threadIdx.x;
    if (p < 16384) {
        int i = p * 256 + tid;
        dev_tohalf(x, hx, NTOK * DDIM / 4, i, 1 << 30);
    } else if (p < 20480) {
        int i = (p - 16384) * 256 + tid;
        dev_interleave(sw1, sw3, swg, 2 * DDIM * HDIM / 4, i, 1 << 30);
    } else if (p < 20512) {
        int i = (p - 20480) * 256 + tid;
        if (i < NTOK * 2) pos[i] = -1;
    } else {
        if (tid < NEXP) { cnt[tid] = 0; mk[tid] = 0; }
    }
}

__global__ void assign_kernel(const int* __restrict__ topi, const float* __restrict__ wts,
                              int* __restrict__ cnt, int* __restrict__ tokl,
                              float* __restrict__ wl) {
    int i = blockIdx.x * blockDim.x + threadIdx.x;
    if (i >= NTOK * 2) return;
    int e = topi[i];
    int p = atomicAdd(&cnt[e], 1);
    tokl[(size_t)e * NTOK + p] = i >> 1;
    wl  [(size_t)e * NTOK + p] = wts[i];
}

__device__ __forceinline__ unsigned fkey(float f) {
    unsigned u = __float_as_uint(f);
    return (u & 0x80000000u) ? ~u : (u | 0x80000000u);
}

// selection + inverse position map: pos[token*2 + which] = e*CAP + slot
__global__ void select_kernel(const int* __restrict__ cnt, const int* __restrict__ tokl,
                              const float* __restrict__ wl, const int* __restrict__ topi,
                              int* __restrict__ ktok, float* __restrict__ kw,
                              int* __restrict__ mk, int* __restrict__ pos) {
    int e = blockIdx.x;
    int n = cnt[e];
    const int*   tl = tokl + (size_t)e * NTOK;
    const float* wv = wl   + (size_t)e * NTOK;
    int tid = threadIdx.x;

    if (n <= CAP) {
        for (int i = tid; i < n; i += blockDim.x) {
            int tkn = tl[i];
            ktok[(size_t)e * CAP + i] = tkn;
            kw  [(size_t)e * CAP + i] = wv[i];
            int which = (topi[tkn * 2] == e) ? 0 : 1;
            pos[tkn * 2 + which] = e * CAP + i;
        }
        if (tid == 0) mk[e] = n;
        return;
    }
    __shared__ int hist[256];
    __shared__ unsigned s_prefix;
    __shared__ int s_rem, s_nk, s_neq;
    __shared__ int eq_tok[2048];
    __shared__ int eq_src[2048];
    if (tid == 0) { s_prefix = 0u; s_rem = CAP; }
    __syncthreads();
    for (int shift = 24; shift >= 0; shift -= 8) {
        for (int b = tid; b < 256; b += blockDim.x) hist[b] = 0;
        __syncthreads();
        unsigned pfx = s_prefix;
        for (int i = tid; i < n; i += blockDim.x) {
            unsigned key = fkey(wv[i]);
            if (shift == 24 || (key >> (shift + 8)) == pfx)
                atomicAdd(&hist[(key >> shift) & 255], 1);
        }
        __syncthreads();
        if (tid == 0) {
            int rem = s_rem;
            int b = 255;
            for (; b > 0; b--) { if (hist[b] >= rem) break; rem -= hist[b]; }
            s_prefix = (pfx << 8) | (unsigned)b;
            s_rem = rem;
        }
        __syncthreads();
    }
    unsigned T = s_prefix;
    int rem = s_rem;
    if (tid == 0) { s_nk = 0; s_neq = 0; }
    __syncthreads();
    for (int i = tid; i < n; i += blockDim.x) {
        unsigned key = fkey(wv[i]);
        if (key > T) {
            int p = atomicAdd(&s_nk, 1);
            int tkn = tl[i];
            ktok[(size_t)e * CAP + p] = tkn;
            kw  [(size_t)e * CAP + p] = wv[i];
            int which = (topi[tkn * 2] == e) ? 0 : 1;
            pos[tkn * 2 + which] = e * CAP + p;
        } else if (key == T) {
            int p = atomicAdd(&s_neq, 1);
            if (p < 2048) { eq_tok[p] = tl[i]; eq_src[p] = i; }
        }
    }
    __syncthreads();
    int neq = min(s_neq, 2048);
    for (int j = tid; j < neq; j += blockDim.x) {
        int tj = eq_tok[j];
        int rank = 0;
        for (int l = 0; l < neq; l++) rank += (eq_tok[l] < tj);
        if (rank < rem) {
            int p = atomicAdd(&s_nk, 1);
            ktok[(size_t)e * CAP + p] = tj;
            kw  [(size_t)e * CAP + p] = wv[eq_src[j]];
            int which = (topi[tj * 2] == e) ? 0 : 1;
            pos[tj * 2 + which] = e * CAP + p;
        }
    }
    __syncthreads();
    if (tid == 0) mk[e] = s_nk;
}

// ---------------- shared GEMM core: C = A[M,K] @ B[K,N] ----------------
// CTA tile 128x128, 8 warps (2m x 4n, warp tile 64x32), KC=64,
// 3-stage cp.async pipeline, fp32 accumulators. Caller pre-offsets A/B/Cv/gl/rw by z.
// MODE 2: C(float)[r][c] = acc*scale
// MODE 3: C(half) [r][c] = acc*rw[r]*scale
// MODE 5: fused SwiGLU: B interleaved (w1|w3); C(half)[r][c/2] = silu(v0)*v1
template<int MODE, bool GATHER>
__device__ __forceinline__ void gemm_core(
    const __half* __restrict__ A, int lda,
    const __half* __restrict__ B,
    void* __restrict__ Cv, int ldc,
    int M, int N, int K,
    const int* __restrict__ gl, const float* __restrict__ rw,
    float outscale, int row0, int col0, char* smem)
{
    __half* Ch = (__half*)Cv;
    float*  Cf = (float*)Cv;

    int tid = threadIdx.x;
    int lane = tid & 31, wid = tid >> 5;
    int wm = wid >> 2, wn = wid & 3;
    int g = lane >> 2, t4 = lane & 3;

    int arow = tid >> 1, aseg = tid & 1;
    const __half* aptr = A;
    int asz = 0;
    {
        int r = row0 + arow;
        if (r < M) {
            int gr = GATHER ? gl[r] : r;
            aptr = A + (size_t)gr * lda + aseg * 32;
            asz = 16;
        }
    }
    int bkrow = tid >> 2, bseg = tid & 3;
    const __half* bptr = B + (size_t)bkrow * N + col0 + bseg * 32;
    uint32_t sbase = (uint32_t)__cvta_generic_to_shared(smem);
    uint32_t aoff = (uint32_t)arow * A_ROWB + (uint32_t)aseg * 64;
    uint32_t boff = (uint32_t)A_BYTES + (uint32_t)bkrow * B_ROWB + (uint32_t)bseg * 64;

    uint32_t a_lm = (uint32_t)(wm * 64 + (lane & 15)) * A_ROWB + (uint32_t)(lane >> 4) * 16;
    uint32_t b_lm = (uint32_t)A_BYTES
                  + (uint32_t)((((lane >> 3) & 1) * 8 + (lane & 7))) * B_ROWB
                  + (uint32_t)(wn * 32 + (lane >> 4) * 8) * 2;

    float acc[4][4][4];
#pragma unroll
    for (int mt = 0; mt < 4; mt++)
#pragma unroll
        for (int nt = 0; nt < 4; nt++)
#pragma unroll
            for (int q = 0; q < 4; q++) acc[mt][nt][q] = 0.f;

    int nk = K / KC;

#define ISSUE_STAGE(KB) do { \
    uint32_t bs_ = (uint32_t)((KB) % NSTAGE) * BUF_BYTES; \
    const __half* as_ = aptr + (KB) * KC; \
    const __half* bs2_ = bptr + (size_t)(KB) * KC * N; \
    uint32_t dA_ = sbase + bs_ + aoff; \
    uint32_t dB_ = sbase + bs_ + boff; \
    _Pragma("unroll") \
    for (int c_ = 0; c_ < 4; c_++) cpasync16(dA_ + c_ * 16, as_ + c_ * 8, asz); \
    _Pragma("unroll") \
    for (int c_ = 0; c_ < 4; c_++) cpasync16(dB_ + c_ * 16, bs2_ + c_ * 8, 16); \
} while (0)

    ISSUE_STAGE(0); CP_COMMIT();
    ISSUE_STAGE(1); CP_COMMIT();

#pragma unroll 1
    for (int kb = 0; kb < nk; kb++) {
        asm volatile("cp.async.wait_group 1;" ::: "memory");
        __syncthreads();
        if (kb + 2 < nk) ISSUE_STAGE(kb + 2);
        CP_COMMIT();

        uint32_t bufb = sbase + (uint32_t)(kb % NSTAGE) * BUF_BYTES;
#pragma unroll
        for (int ks = 0; ks < 4; ks++) {
            uint32_t af[4][4], bf[4][2];
#pragma unroll
            for (int mt = 0; mt < 4; mt++) {
                uint32_t ad = bufb + a_lm + (uint32_t)mt * (16 * A_ROWB) + (uint32_t)ks * 32;
                asm volatile("ldmatrix.sync.aligned.m8n8.x4.shared.b16 {%0,%1,%2,%3}, [%4];"
                             : "=r"(af[mt][0]), "=r"(af[mt][1]), "=r"(af[mt][2]), "=r"(af[mt][3])
                             : "r"(ad));
            }
#pragma unroll
            for (int p = 0; p < 2; p++) {
                uint32_t bd = bufb + b_lm + (uint32_t)ks * (16 * B_ROWB) + (uint32_t)p * 32;
                asm volatile("ldmatrix.sync.aligned.m8n8.x4.trans.shared.b16 {%0,%1,%2,%3}, [%4];"
                             : "=r"(bf[2*p][0]), "=r"(bf[2*p][1]),
                               "=r"(bf[2*p+1][0]), "=r"(bf[2*p+1][1])
                             : "r"(bd));
            }
#pragma unroll
            for (int mt = 0; mt < 4; mt++)
#pragma unroll
                for (int nt = 0; nt < 4; nt++)
                    asm volatile(
                        "mma.sync.aligned.m16n8k16.row.col.f32.f16.f16.f32 "
                        "{%0,%1,%2,%3}, {%4,%5,%6,%7}, {%8,%9}, {%0,%1,%2,%3};"
                        : "+f"(acc[mt][nt][0]), "+f"(acc[mt][nt][1]),
                          "+f"(acc[mt][nt][2]), "+f"(acc[mt][nt][3])
                        : "r"(af[mt][0]), "r"(af[mt][1]), "r"(af[mt][2]), "r"(af[mt][3]),
                          "r"(bf[nt][0]), "r"(bf[nt][1]));
        }
    }
#undef ISSUE_STAGE

    // epilogue
#pragma unroll
    for (int mt = 0; mt < 4; mt++) {
#pragma unroll
        for (int h = 0; h < 2; h++) {
            int rr = row0 + wm * 64 + mt * 16 + g + h * 8;
            if (rr >= M) continue;
            float scl = outscale;
            if (MODE == 3) scl = rw[rr] * outscale;
#pragma unroll
            for (int nt = 0; nt < 4; nt++) {
                int cc = col0 + wn * 32 + nt * 8 + t4 * 2;
                float v0 = acc[mt][nt][h * 2 + 0];
                float v1 = acc[mt][nt][h * 2 + 1];
                if (MODE == 2) {
                    size_t off = (size_t)rr * ldc + cc;
                    *reinterpret_cast<float2*>(Cf + off) =
                        make_float2(v0 * outscale, v1 * outscale);
                } else if (MODE == 3) {
                    size_t off = (size_t)rr * ldc + cc;
                    *reinterpret_cast<__half2*>(Ch + off) =
                        __floats2half2_rn(v0 * scl, v1 * scl);
                } else { // MODE 5
                    float sv = v0 / (1.f + __expf(-v0)) * v1;
                    Ch[(size_t)rr * ldc + (cc >> 1)] = __float2half_rn(sv);
                }
            }
        }
    }
}

// ---------------- GEMM wrapper (GEMM1 fat w/ prep slice; GEMM4) ----------------
template<int MODE, bool GATHER, bool PREP>
__global__ void __launch_bounds__(256, 2)
gemm_h(const __half* __restrict__ A, size_t sAz, int lda,
       const __half* __restrict__ B, size_t sBz,
       void* __restrict__ Cv, size_t sCz, int ldc,
       const int* __restrict__ mlist, int Mmax, int N, int K,
       const int* __restrict__ gidx, const float* __restrict__ roww,
       float outscale, int Zmain, PrepArgs pa)
{
    extern __shared__ char smem[];
    if (PREP && blockIdx.z == (unsigned)Zmain) {
        prep_dispatch(pa);
        return;
    }
    int z = blockIdx.z;
    int M = mlist ? mlist[z] : Mmax;
    int row0 = blockIdx.y * BM;
    if (row0 >= M) return;
    int col0 = blockIdx.x * BN;

    const int*   gl = gidx ? gidx + (size_t)z * CAP : nullptr;
    const float* rw = roww ? roww + (size_t)z * CAP : nullptr;
    void* Cz = (MODE == 2) ? Cv : (void*)((__half*)Cv + sCz * z);

    gemm_core<MODE, GATHER>(A + sAz * z, lda, B + sBz * z, Cz, ldc,
                            M, N, K, gl, rw, outscale, row0, col0, smem);
}

// ---------------- fused middle launch: shared-down (z=0,1) + routed-up (z=2..17) ----
__global__ void __launch_bounds__(256, 2)
gemm_dual(const __half* __restrict__ hx, const __half* __restrict__ wg,
          __half* __restrict__ act2, const int* __restrict__ mk,
          const int* __restrict__ ktok,
          const __half* __restrict__ actS, const __half* __restrict__ sw2h,
          float* __restrict__ out)
{
    extern __shared__ char smem[];
    if (blockIdx.z < 2) {
        // shared-down: C(float) = act[NTOK][2H] @ sw2h[2H][D] * 0.5 ; 1024 tiles (8 x 128)
        int p = blockIdx.z * 640 + blockIdx.y * 32 + blockIdx.x;
        if (p >= (DDIM / BN) * (NTOK / BM)) return;
        int by = p >> 3, bx = p & 7;
        gemm_core<2, false>(actS, 2 * HDIM, sw2h, out, DDIM,
                            NTOK, DDIM, 2 * HDIM, nullptr, nullptr,
                            0.5f, by * BM, bx * BN, smem);
    } else {
        // routed-up fused SwiGLU: act2[e] = swiglu-mix(hx[ktok] @ wg[e])
        int z = blockIdx.z - 2;
        int M = mk[z];
        int row0 = blockIdx.y * BM;
        if (row0 >= M) return;
        gemm_core<5, true>(hx, DDIM, wg + (size_t)z * DDIM * 2 * HDIM,
                           act2 + (size_t)z * CAP * HDIM, HDIM,
                           M, 2 * HDIM, DDIM, ktok + (size_t)z * CAP, nullptr,
                           1.f, row0, blockIdx.x * BN, smem);
    }
}

// ---------------- final combine: out[t] += y[pos0] + y[pos1] ----------------
__global__ void combine_kernel(const int* __restrict__ pos, const __half* __restrict__ y,
                               float* __restrict__ out) {
    int i = blockIdx.x * blockDim.x + threadIdx.x;
    int tok = i >> 8;
    int c = (i & 255) * 4;
    int p0 = pos[tok * 2], p1 = pos[tok * 2 + 1];
    float4 o = *reinterpret_cast<float4*>(out + (size_t)tok * DDIM + c);
    if (p0 >= 0) {
        __half2 a = *reinterpret_cast<const __half2*>(y + (size_t)p0 * DDIM + c);
        __half2 b = *reinterpret_cast<const __half2*>(y + (size_t)p0 * DDIM + c + 2);
        o.x += __low2float(a); o.y += __high2float(a);
        o.z += __low2float(b); o.w += __high2float(b);
    }
    if (p1 >= 0) {
        __half2 a = *reinterpret_cast<const __half2*>(y + (size_t)p1 * DDIM + c);
        __half2 b = *reinterpret_cast<const __half2*>(y + (size_t)p1 * DDIM + c + 2);
        o.x += __low2float(a); o.y += __high2float(a);
        o.z += __low2float(b); o.w += __high2float(b);
    }
    *reinterpret_cast<float4*>(out + (size_t)tok * DDIM + c) = o;
}

// ---------------- host launcher ----------------
extern "C" void kernel_launch(void* const* d_in, const int* in_sizes, int n_in,
                              void* d_out, int out_size) {
    const float* x   = (const float*)d_in[0];
    const float* gw  = (const float*)d_in[1];
    const float* gb  = (const float*)d_in[2];
    const float* ew1 = (const float*)d_in[3];
    const float* ew3 = (const float*)d_in[4];
    const float* ew2 = (const float*)d_in[5];
    const float* sw1 = (const float*)d_in[6];
    const float* sw3 = (const float*)d_in[7];
    const float* sw2 = (const float*)d_in[8];
    float* out = (float*)d_out;

    __half *act, *act2, *yb, *hx, *wg, *swg, *w2h, *sw2h;
    float *wts, *wl, *kw;
    int *topi, *cnt, *tokl, *ktok, *mk, *pos;
    cudaGetSymbolAddress((void**)&act,  g_act);
    cudaGetSymbolAddress((void**)&act2, g_act2);
    cudaGetSymbolAddress((void**)&yb,   g_y);
    cudaGetSymbolAddress((void**)&hx,   g_hx);
    cudaGetSymbolAddress((void**)&wg,   g_wg);
    cudaGetSymbolAddress((void**)&swg,  g_swg);
    cudaGetSymbolAddress((void**)&w2h,  g_w2h);
    cudaGetSymbolAddress((void**)&sw2h, g_sw2h);
    cudaGetSymbolAddress((void**)&topi, g_topi);
    cudaGetSymbolAddress((void**)&wts,  g_wts);
    cudaGetSymbolAddress((void**)&cnt,  g_cnt);
    cudaGetSymbolAddress((void**)&tokl, g_tokl);
    cudaGetSymbolAddress((void**)&wl,   g_wl);
    cudaGetSymbolAddress((void**)&ktok, g_ktok);
    cudaGetSymbolAddress((void**)&kw,   g_kw);
    cudaGetSymbolAddress((void**)&mk,   g_mk);
    cudaGetSymbolAddress((void**)&pos,  g_pos);

    PrepArgs pa;
    pa.x = x; pa.gw = gw; pa.gb = gb;
    pa.ew1 = ew1; pa.ew3 = ew3; pa.ew2 = ew2; pa.sw2 = sw2;
    pa.wg = wg; pa.w2h = w2h; pa.sw2h = sw2h;
    pa.topi = topi; pa.wts = wts;
    PrepArgs pz = {};

    cudaFuncSetAttribute((const void*)gemm_h<5,false,true>,  cudaFuncAttributeMaxDynamicSharedMemorySize, SMEM_BYTES);
    cudaFuncSetAttribute((const void*)gemm_h<3,false,false>, cudaFuncAttributeMaxDynamicSharedMemorySize, SMEM_BYTES);
    cudaFuncSetAttribute((const void*)gemm_dual,             cudaFuncAttributeMaxDynamicSharedMemorySize, SMEM_BYTES);

    // 0: consolidated front-end (hx convert, swg interleave, pos/cnt/mk init)
    prep0_kernel<<<20513, 256>>>(x, hx, sw1, sw3, swg, pos, cnt, mk);

    // 1: FAT shared fused-up GEMM (z=0,1) + prep slice (z=2): gate, interleave wg,
    //    tohalf w2h, tohalf sw2h — hidden under tensor-bound GEMM work.
    gemm_h<5,false,true><<<dim3(2*HDIM/BN, NTOK/BM, 3), 256, SMEM_BYTES>>>(
        hx, 0, DDIM, swg, (size_t)DDIM*2*HDIM, act, (size_t)HDIM, 2*HDIM,
        nullptr, NTOK, 2*HDIM, DDIM, nullptr, nullptr, 1.f, 2, pa);

    // 2: expert membership lists (needs gate output)
    assign_kernel<<<(NTOK * 2 + 255) / 256, 256>>>(topi, wts, cnt, tokl, wl);

    // 3: capacity selection
    select_kernel<<<NEXP, 256>>>(cnt, tokl, wl, topi, ktok, kw, mk, pos);

    // 4: FUSED middle launch — shared-down (long-K tiles first, z=0,1) + routed-up
    gemm_dual<<<dim3(2*HDIM/BN, CAP/BM, NEXP + 2), 256, SMEM_BYTES>>>(
        hx, wg, act2, mk, ktok, act, sw2h, out);

    // 5: routed down-proj into y staging
    gemm_h<3,false,false><<<dim3(DDIM/BN, CAP/BM, NEXP), 256, SMEM_BYTES>>>(
        act2, (size_t)CAP*HDIM, HDIM, w2h, (size_t)HDIM*DDIM, yb, (size_t)CAP*DDIM, DDIM,
        mk, CAP, DDIM, HDIM, nullptr, kw, 1.f, -1, pz);

    // 6: final gather-sum (no atomics)
    combine_kernel<<<NTOK * 256 / 256, 256>>>(pos, yb, out);
}

// round 17
// speedup vs baseline: 1.0146x; 1.0055x over previous
#include <cuda_runtime.h>
#include <cuda_fp16.h>
#include <cstdint>

#define NTOK 16384
#define DDIM 1024
#define HDIM 2048
#define NEXP 16
#define CAP  2560
#define BM 128
#define BN 128
#define KC 64
#define A_ROWB 144                   // 64 halves + 8 pad, bytes
#define B_ROWB 272                   // 128 halves + 8 pad, bytes
#define A_BYTES (BM * A_ROWB)        // 18432
#define B_BYTES (KC * B_ROWB)        // 17408
#define BUF_BYTES (A_BYTES + B_BYTES)
#define NSTAGE 3
#define SMEM_BYTES (NSTAGE * BUF_BYTES)  // 107520 -> 2 CTAs/SM

// ---------------- scratch (device globals; no allocation) ----------------
__device__ __half g_act  [(size_t)NEXP * CAP * HDIM];       // shared-phase act [NTOK][2H]
__device__ __half g_act2 [(size_t)NEXP * CAP * HDIM];       // routed act [e][CAP][H]
__device__ __half g_y    [(size_t)NEXP * CAP * DDIM];       // routed y staging
__device__ __half g_hx   [(size_t)NTOK * DDIM];
__device__ __half g_wg   [(size_t)NEXP * DDIM * 2 * HDIM];  // interleaved w1/w3
__device__ __half g_swg  [(size_t)2 * DDIM * 2 * HDIM];     // interleaved sw1/sw3
__device__ __half g_w2h  [(size_t)NEXP * HDIM * DDIM];
__device__ __half g_sw2h [(size_t)2 * HDIM * DDIM];
__device__ int    g_topi[NTOK * 2];
__device__ float  g_wts [NTOK * 2];
__device__ int    g_cnt [NEXP];
__device__ int    g_tokl[NEXP * NTOK];
__device__ float  g_wl  [NEXP * NTOK];
__device__ int    g_ktok[NEXP * CAP];
__device__ float  g_kw  [NEXP * CAP];
__device__ int    g_mk  [NEXP];
__device__ int    g_pos [NTOK * 2];

// prep-work argument bundle (passed by value to the fat GEMM1 launch)
struct PrepArgs {
    const float *x, *gw, *gb, *ew1, *ew3, *ew2, *sw2;
    __half *wg, *w2h, *sw2h;
    int *topi;
    float *wts;
};

// ---------------- helpers ----------------
__device__ __forceinline__ void cpasync16(uint32_t dst, const void* src, int srcsz) {
    asm volatile("cp.async.cg.shared.global [%0], [%1], 16, %2;"
                 :: "r"(dst), "l"(src), "r"(srcsz));
}
#define CP_COMMIT() asm volatile("cp.async.commit_group;" ::: "memory")

// ---------------- prep device helpers ----------------
__device__ __forceinline__ void dev_interleave(const float* w1, const float* w3,
                                               __half* wg, int n4, int start, int stride) {
    for (int i = start; i < n4; i += stride) {
        float4 a = reinterpret_cast<const float4*>(w1)[i];
        float4 b = reinterpret_cast<const float4*>(w3)[i];
        __half2 h0 = __floats2half2_rn(a.x, b.x);
        __half2 h1 = __floats2half2_rn(a.y, b.y);
        __half2 h2 = __floats2half2_rn(a.z, b.z);
        __half2 h3 = __floats2half2_rn(a.w, b.w);
        uint4 o;
        o.x = *reinterpret_cast<uint32_t*>(&h0);
        o.y = *reinterpret_cast<uint32_t*>(&h1);
        o.z = *reinterpret_cast<uint32_t*>(&h2);
        o.w = *reinterpret_cast<uint32_t*>(&h3);
        reinterpret_cast<uint4*>(wg)[i] = o;
    }
}

__device__ __forceinline__ void dev_tohalf(const float* s, __half* o, int n4,
                                           int start, int stride) {
    for (int i = start; i < n4; i += stride) {
        float4 v = reinterpret_cast<const float4*>(s)[i];
        __half2* o2 = reinterpret_cast<__half2*>(o);
        o2[i * 2 + 0] = __floats2half2_rn(v.x, v.y);
        o2[i * 2 + 1] = __floats2half2_rn(v.z, v.w);
    }
}

__device__ __forceinline__ void dev_gate1(const PrepArgs& pa, int t) {
    int lane = threadIdx.x & 31;
    if (t >= NTOK) return;
    const float* xr = pa.x + (size_t)t * DDIM;
    float s[NEXP];
#pragma unroll
    for (int e = 0; e < NEXP; e++) s[e] = 0.f;
    for (int i = lane; i < DDIM; i += 32) {
        float xv = xr[i];
        const float4* w4 = reinterpret_cast<const float4*>(pa.gw + (size_t)i * NEXP);
#pragma unroll
        for (int q = 0; q < 4; q++) {
            float4 w = w4[q];
            s[q*4+0] += xv * w.x; s[q*4+1] += xv * w.y;
            s[q*4+2] += xv * w.z; s[q*4+3] += xv * w.w;
        }
    }
#pragma unroll
    for (int e = 0; e < NEXP; e++)
#pragma unroll
        for (int off = 16; off > 0; off >>= 1)
            s[e] += __shfl_xor_sync(0xffffffffu, s[e], off);
    if (lane == 0) {
        float mx = s[0];
#pragma unroll
        for (int e = 1; e < NEXP; e++) mx = fmaxf(mx, s[e]);
        float sum = 0.f, sc[NEXP];
#pragma unroll
        for (int e = 0; e < NEXP; e++) { sc[e] = expf(s[e] - mx); sum += sc[e]; }
        float inv = 1.f / sum;
#pragma unroll
        for (int e = 0; e < NEXP; e++) sc[e] = sc[e] * inv + pa.gb[e];
        int i0 = 0; float v0 = sc[0];
#pragma unroll
        for (int e = 1; e < NEXP; e++) if (sc[e] > v0) { v0 = sc[e]; i0 = e; }
        int i1 = 0; float v1 = -1e30f;
#pragma unroll
        for (int e = 0; e < NEXP; e++) if (e != i0 && sc[e] > v1) { v1 = sc[e]; i1 = e; }
        pa.topi[t*2+0] = i0; pa.topi[t*2+1] = i1;
        pa.wts [t*2+0] = s[i0]; pa.wts[t*2+1] = s[i1];
    }
}

__device__ __forceinline__ void prep_dispatch(const PrepArgs& pa) {
    int p = blockIdx.y * gridDim.x + blockIdx.x;
    int tid = threadIdx.x;
    if (p < 1024) {                       // gate: 16 tokens per block (2 per warp)
        int w = tid >> 5;
        dev_gate1(pa, p * 16 + w);
        dev_gate1(pa, p * 16 + 8 + w);
    } else if (p < 1536) {                // interleave ew1/ew3 -> wg
        int bid = p - 1024;
        dev_interleave(pa.ew1, pa.ew3, pa.wg, NEXP*DDIM*HDIM/4,
                       bid * 256 + tid, 512 * 256);
    } else if (p < 1792) {                // tohalf ew2 -> w2h
        int bid = p - 1536;
        dev_tohalf(pa.ew2, pa.w2h, NEXP*HDIM*DDIM/4, bid * 256 + tid, 256 * 256);
    } else if (p < 1824) {                // tohalf sw2 -> sw2h
        int bid = p - 1792;
        dev_tohalf(pa.sw2, pa.sw2h, 2*HDIM*DDIM/4, bid * 256 + tid, 32 * 256);
    }
}

// ---------------- consolidated front-end prep (one launch) ----------------
__global__ void prep0_kernel(const float* __restrict__ x, __half* __restrict__ hx,
                             const float* __restrict__ sw1, const float* __restrict__ sw3,
                             __half* __restrict__ swg,
                             int* __restrict__ pos, int* __restrict__ cnt,
                             int* __restrict__ mk) {
    int p = blockIdx.x;
    int tid = threadIdx.x;
    if (p < 16384) {
        int i = p * 256 + tid;
        dev_tohalf(x, hx, NTOK * DDIM / 4, i, 1 << 30);
    } else if (p < 20480) {
        int i = (p - 16384) * 256 + tid;
        dev_interleave(sw1, sw3, swg, 2 * DDIM * HDIM / 4, i, 1 << 30);
    } else if (p < 20512) {
        int i = (p - 20480) * 256 + tid;
        if (i < NTOK * 2) pos[i] = -1;
    } else {
        if (tid < NEXP) { cnt[tid] = 0; mk[tid] = 0; }
    }
}

__global__ void assign_kernel(const int* __restrict__ topi, const float* __restrict__ wts,
                              int* __restrict__ cnt, int* __restrict__ tokl,
                              float* __restrict__ wl) {
    int i = blockIdx.x * blockDim.x + threadIdx.x;
    if (i >= NTOK * 2) return;
    int e = topi[i];
    int p = atomicAdd(&cnt[e], 1);
    tokl[(size_t)e * NTOK + p] = i >> 1;
    wl  [(size_t)e * NTOK + p] = wts[i];
}

__device__ __forceinline__ unsigned fkey(float f) {
    unsigned u = __float_as_uint(f);
    return (u & 0x80000000u) ? ~u : (u | 0x80000000u);
}

// selection + inverse position map: pos[token*2 + which] = e*CAP + slot
__global__ void select_kernel(const int* __restrict__ cnt, const int* __restrict__ tokl,
                              const float* __restrict__ wl, const int* __restrict__ topi,
                              int* __restrict__ ktok, float* __restrict__ kw,
                              int* __restrict__ mk, int* __restrict__ pos) {
    int e = blockIdx.x;
    int n = cnt[e];
    const int*   tl = tokl + (size_t)e * NTOK;
    const float* wv = wl   + (size_t)e * NTOK;
    int tid = threadIdx.x;

    if (n <= CAP) {
        for (int i = tid; i < n; i += blockDim.x) {
            int tkn = tl[i];
            ktok[(size_t)e * CAP + i] = tkn;
            kw  [(size_t)e * CAP + i] = wv[i];
            int which = (topi[tkn * 2] == e) ? 0 : 1;
            pos[tkn * 2 + which] = e * CAP + i;
        }
        if (tid == 0) mk[e] = n;
        return;
    }
    __shared__ int hist[256];
    __shared__ unsigned s_prefix;
    __shared__ int s_rem, s_nk, s_neq;
    __shared__ int eq_tok[2048];
    __shared__ int eq_src[2048];
    if (tid == 0) { s_prefix = 0u; s_rem = CAP; }
    __syncthreads();
    for (int shift = 24; shift >= 0; shift -= 8) {
        for (int b = tid; b < 256; b += blockDim.x) hist[b] = 0;
        __syncthreads();
        unsigned pfx = s_prefix;
        for (int i = tid; i < n; i += blockDim.x) {
            unsigned key = fkey(wv[i]);
            if (shift == 24 || (key >> (shift + 8)) == pfx)
                atomicAdd(&hist[(key >> shift) & 255], 1);
        }
        __syncthreads();
        if (tid == 0) {
            int rem = s_rem;
            int b = 255;
            for (; b > 0; b--) { if (hist[b] >= rem) break; rem -= hist[b]; }
            s_prefix = (pfx << 8) | (unsigned)b;
            s_rem = rem;
        }
        __syncthreads();
    }
    unsigned T = s_prefix;
    int rem = s_rem;
    if (tid == 0) { s_nk = 0; s_neq = 0; }
    __syncthreads();
    for (int i = tid; i < n; i += blockDim.x) {
        unsigned key = fkey(wv[i]);
        if (key > T) {
            int p = atomicAdd(&s_nk, 1);
            int tkn = tl[i];
            ktok[(size_t)e * CAP + p] = tkn;
            kw  [(size_t)e * CAP + p] = wv[i];
            int which = (topi[tkn * 2] == e) ? 0 : 1;
            pos[tkn * 2 + which] = e * CAP + p;
        } else if (key == T) {
            int p = atomicAdd(&s_neq, 1);
            if (p < 2048) { eq_tok[p] = tl[i]; eq_src[p] = i; }
        }
    }
    __syncthreads();
    int neq = min(s_neq, 2048);
    for (int j = tid; j < neq; j += blockDim.x) {
        int tj = eq_tok[j];
        int rank = 0;
        for (int l = 0; l < neq; l++) rank += (eq_tok[l] < tj);
        if (rank < rem) {
            int p = atomicAdd(&s_nk, 1);
            ktok[(size_t)e * CAP + p] = tj;
            kw  [(size_t)e * CAP + p] = wv[eq_src[j]];
            int which = (topi[tj * 2] == e) ? 0 : 1;
            pos[tj * 2 + which] = e * CAP + p;
        }
    }
    __syncthreads();
    if (tid == 0) mk[e] = s_nk;
}

// ---------------- shared GEMM core: C = A[M,K] @ B[K,N] ----------------
// CTA tile 128x128, 8 warps (2m x 4n, warp tile 64x32), KC=64,
// 3-stage cp.async pipeline, fp32 accumulators. Caller pre-offsets A/B/Cv/gl/rw by z.
// MODE 2: C(float)[r][c] = acc*scale
// MODE 3: C(half) [r][c] = acc*rw[r]*scale
// MODE 5: fused SwiGLU: B interleaved (w1|w3); C(half)[r][c/2] = silu(v0)*v1
template<int MODE, bool GATHER>
__device__ __forceinline__ void gemm_core(
    const __half* __restrict__ A, int lda,
    const __half* __restrict__ B,
    void* __restrict__ Cv, int ldc,
    int M, int N, int K,
    const int* __restrict__ gl, const float* __restrict__ rw,
    float outscale, int row0, int col0, char* smem)
{
    __half* Ch = (__half*)Cv;
    float*  Cf = (float*)Cv;

    int tid = threadIdx.x;
    int lane = tid & 31, wid = tid >> 5;
    int wm = wid >> 2, wn = wid & 3;
    int g = lane >> 2, t4 = lane & 3;

    int arow = tid >> 1, aseg = tid & 1;
    const __half* aptr = A;
    int asz = 0;
    {
        int r = row0 + arow;
        if (r < M) {
            int gr = GATHER ? gl[r] : r;
            aptr = A + (size_t)gr * lda + aseg * 32;
            asz = 16;
        }
    }
    int bkrow = tid >> 2, bseg = tid & 3;
    const __half* bptr = B + (size_t)bkrow * N + col0 + bseg * 32;
    uint32_t sbase = (uint32_t)__cvta_generic_to_shared(smem);
    uint32_t aoff = (uint32_t)arow * A_ROWB + (uint32_t)aseg * 64;
    uint32_t boff = (uint32_t)A_BYTES + (uint32_t)bkrow * B_ROWB + (uint32_t)bseg * 64;

    uint32_t a_lm = (uint32_t)(wm * 64 + (lane & 15)) * A_ROWB + (uint32_t)(lane >> 4) * 16;
    uint32_t b_lm = (uint32_t)A_BYTES
                  + (uint32_t)((((lane >> 3) & 1) * 8 + (lane & 7))) * B_ROWB
                  + (uint32_t)(wn * 32 + (lane >> 4) * 8) * 2;

    float acc[4][4][4];
#pragma unroll
    for (int mt = 0; mt < 4; mt++)
#pragma unroll
        for (int nt = 0; nt < 4; nt++)
#pragma unroll
            for (int q = 0; q < 4; q++) acc[mt][nt][q] = 0.f;

    int nk = K / KC;

#define ISSUE_STAGE(KB) do { \
    uint32_t bs_ = (uint32_t)((KB) % NSTAGE) * BUF_BYTES; \
    const __half* as_ = aptr + (KB) * KC; \
    const __half* bs2_ = bptr + (size_t)(KB) * KC * N; \
    uint32_t dA_ = sbase + bs_ + aoff; \
    uint32_t dB_ = sbase + bs_ + boff; \
    _Pragma("unroll") \
    for (int c_ = 0; c_ < 4; c_++) cpasync16(dA_ + c_ * 16, as_ + c_ * 8, asz); \
    _Pragma("unroll") \
    for (int c_ = 0; c_ < 4; c_++) cpasync16(dB_ + c_ * 16, bs2_ + c_ * 8, 16); \
} while (0)

    ISSUE_STAGE(0); CP_COMMIT();
    ISSUE_STAGE(1); CP_COMMIT();

#pragma unroll 1
    for (int kb = 0; kb < nk; kb++) {
        asm volatile("cp.async.wait_group 1;" ::: "memory");
        __syncthreads();
        if (kb + 2 < nk) ISSUE_STAGE(kb + 2);
        CP_COMMIT();

        uint32_t bufb = sbase + (uint32_t)(kb % NSTAGE) * BUF_BYTES;
#pragma unroll
        for (int ks = 0; ks < 4; ks++) {
            uint32_t af[4][4], bf[4][2];
#pragma unroll
            for (int mt = 0; mt < 4; mt++) {
                uint32_t ad = bufb + a_lm + (uint32_t)mt * (16 * A_ROWB) + (uint32_t)ks * 32;
                asm volatile("ldmatrix.sync.aligned.m8n8.x4.shared.b16 {%0,%1,%2,%3}, [%4];"
                             : "=r"(af[mt][0]), "=r"(af[mt][1]), "=r"(af[mt][2]), "=r"(af[mt][3])
                             : "r"(ad));
            }
#pragma unroll
            for (int p = 0; p < 2; p++) {
                uint32_t bd = bufb + b_lm + (uint32_t)ks * (16 * B_ROWB) + (uint32_t)p * 32;
                asm volatile("ldmatrix.sync.aligned.m8n8.x4.trans.shared.b16 {%0,%1,%2,%3}, [%4];"
                             : "=r"(bf[2*p][0]), "=r"(bf[2*p][1]),
                               "=r"(bf[2*p+1][0]), "=r"(bf[2*p+1][1])
                             : "r"(bd));
            }
#pragma unroll
            for (int mt = 0; mt < 4; mt++)
#pragma unroll
                for (int nt = 0; nt < 4; nt++)
                    asm volatile(
                        "mma.sync.aligned.m16n8k16.row.col.f32.f16.f16.f32 "
                        "{%0,%1,%2,%3}, {%4,%5,%6,%7}, {%8,%9}, {%0,%1,%2,%3};"
                        : "+f"(acc[mt][nt][0]), "+f"(acc[mt][nt][1]),
                          "+f"(acc[mt][nt][2]), "+f"(acc[mt][nt][3])
                        : "r"(af[mt][0]), "r"(af[mt][1]), "r"(af[mt][2]), "r"(af[mt][3]),
                          "r"(bf[nt][0]), "r"(bf[nt][1]));
        }
    }
#undef ISSUE_STAGE

    // epilogue
#pragma unroll
    for (int mt = 0; mt < 4; mt++) {
#pragma unroll
        for (int h = 0; h < 2; h++) {
            int rr = row0 + wm * 64 + mt * 16 + g + h * 8;
            if (rr >= M) continue;
            float scl = outscale;
            if (MODE == 3) scl = rw[rr] * outscale;
#pragma unroll
            for (int nt = 0; nt < 4; nt++) {
                int cc = col0 + wn * 32 + nt * 8 + t4 * 2;
                float v0 = acc[mt][nt][h * 2 + 0];
                float v1 = acc[mt][nt][h * 2 + 1];
                if (MODE == 2) {
                    size_t off = (size_t)rr * ldc + cc;
                    *reinterpret_cast<float2*>(Cf + off) =
                        make_float2(v0 * outscale, v1 * outscale);
                } else if (MODE == 3) {
                    size_t off = (size_t)rr * ldc + cc;
                    *reinterpret_cast<__half2*>(Ch + off) =
                        __floats2half2_rn(v0 * scl, v1 * scl);
                } else { // MODE 5
                    float sv = v0 / (1.f + __expf(-v0)) * v1;
                    Ch[(size_t)rr * ldc + (cc >> 1)] = __float2half_rn(sv);
                }
            }
        }
    }
}

// ---------------- GEMM wrapper (GEMM1 fat w/ prep slice; GEMM4) ----------------
template<int MODE, bool GATHER, bool PREP>
__global__ void __launch_bounds__(256, 2)
gemm_h(const __half* __restrict__ A, size_t sAz, int lda,
       const __half* __restrict__ B, size_t sBz,
       void* __restrict__ Cv, size_t sCz, int ldc,
       const int* __restrict__ mlist, int Mmax, int N, int K,
       const int* __restrict__ gidx, const float* __restrict__ roww,
       float outscale, int Zmain, PrepArgs pa)
{
    extern __shared__ char smem[];
    if (PREP && blockIdx.z == (unsigned)Zmain) {
        prep_dispatch(pa);
        return;
    }
    int z = blockIdx.z;
    int M = mlist ? mlist[z] : Mmax;
    int row0 = blockIdx.y * BM;
    if (row0 >= M) return;
    int col0 = blockIdx.x * BN;

    const int*   gl = gidx ? gidx + (size_t)z * CAP : nullptr;
    const float* rw = roww ? roww + (size_t)z * CAP : nullptr;
    void* Cz = (MODE == 2) ? Cv : (void*)((__half*)Cv + sCz * z);

    gemm_core<MODE, GATHER>(A + sAz * z, lda, B + sBz * z, Cz, ldc,
                            M, N, K, gl, rw, outscale, row0, col0, smem);
}

// ---------------- fused middle launch: shared-down (z=0,1) + routed-up (z=2..17) ----
__global__ void __launch_bounds__(256, 2)
gemm_dual(const __half* __restrict__ hx, const __half* __restrict__ wg,
          __half* __restrict__ act2, const int* __restrict__ mk,
          const int* __restrict__ ktok,
          const __half* __restrict__ actS, const __half* __restrict__ sw2h,
          float* __restrict__ out)
{
    extern __shared__ char smem[];
    if (blockIdx.z < 2) {
        // shared-down: C(float) = act[NTOK][2H] @ sw2h[2H][D] * 0.5 ; 1024 tiles (8 x 128)
        int p = blockIdx.z * 640 + blockIdx.y * 32 + blockIdx.x;
        if (p >= (DDIM / BN) * (NTOK / BM)) return;
        int by = p >> 3, bx = p & 7;
        gemm_core<2, false>(actS, 2 * HDIM, sw2h, out, DDIM,
                            NTOK, DDIM, 2 * HDIM, nullptr, nullptr,
                            0.5f, by * BM, bx * BN, smem);
    } else {
        // routed-up fused SwiGLU: act2[e] = swiglu-mix(hx[ktok] @ wg[e])
        int z = blockIdx.z - 2;
        int M = mk[z];
        int row0 = blockIdx.y * BM;
        if (row0 >= M) return;
        gemm_core<5, true>(hx, DDIM, wg + (size_t)z * DDIM * 2 * HDIM,
                           act2 + (size_t)z * CAP * HDIM, HDIM,
                           M, 2 * HDIM, DDIM, ktok + (size_t)z * CAP, nullptr,
                           1.f, row0, blockIdx.x * BN, smem);
    }
}

// ---------------- final combine: out[t] += y[pos0] + y[pos1] ----------------
__global__ void combine_kernel(const int* __restrict__ pos, const __half* __restrict__ y,
                               float* __restrict__ out) {
    int i = blockIdx.x * blockDim.x + threadIdx.x;
    int tok = i >> 8;
    int c = (i & 255) * 4;
    int p0 = pos[tok * 2], p1 = pos[tok * 2 + 1];
    float4 o = *reinterpret_cast<float4*>(out + (size_t)tok * DDIM + c);
    if (p0 >= 0) {
        __half2 a = *reinterpret_cast<const __half2*>(y + (size_t)p0 * DDIM + c);
        __half2 b = *reinterpret_cast<const __half2*>(y + (size_t)p0 * DDIM + c + 2);
        o.x += __low2float(a); o.y += __high2float(a);
        o.z += __low2float(b); o.w += __high2float(b);
    }
    if (p1 >= 0) {
        __half2 a = *reinterpret_cast<const __half2*>(y + (size_t)p1 * DDIM + c);
        __half2 b = *reinterpret_cast<const __half2*>(y + (size_t)p1 * DDIM + c + 2);
        o.x += __low2float(a); o.y += __high2float(a);
        o.z += __low2float(b); o.w += __high2float(b);
    }
    *reinterpret_cast<float4*>(out + (size_t)tok * DDIM + c) = o;
}

// ---------------- host launcher ----------------
extern "C" void kernel_launch(void* const* d_in, const int* in_sizes, int n_in,
                              void* d_out, int out_size) {
    const float* x   = (const float*)d_in[0];
    const float* gw  = (const float*)d_in[1];
    const float* gb  = (const float*)d_in[2];
    const float* ew1 = (const float*)d_in[3];
    const float* ew3 = (const float*)d_in[4];
    const float* ew2 = (const float*)d_in[5];
    const float* sw1 = (const float*)d_in[6];
    const float* sw3 = (const float*)d_in[7];
    const float* sw2 = (const float*)d_in[8];
    float* out = (float*)d_out;

    __half *act, *act2, *yb, *hx, *wg, *swg, *w2h, *sw2h;
    float *wts, *wl, *kw;
    int *topi, *cnt, *tokl, *ktok, *mk, *pos;
    cudaGetSymbolAddress((void**)&act,  g_act);
    cudaGetSymbolAddress((void**)&act2, g_act2);
    cudaGetSymbolAddress((void**)&yb,   g_y);
    cudaGetSymbolAddress((void**)&hx,   g_hx);
    cudaGetSymbolAddress((void**)&wg,   g_wg);
    cudaGetSymbolAddress((void**)&swg,  g_swg);
    cudaGetSymbolAddress((void**)&w2h,  g_w2h);
    cudaGetSymbolAddress((void**)&sw2h, g_sw2h);
    cudaGetSymbolAddress((void**)&topi, g_topi);
    cudaGetSymbolAddress((void**)&wts,  g_wts);
    cudaGetSymbolAddress((void**)&cnt,  g_cnt);
    cudaGetSymbolAddress((void**)&tokl, g_tokl);
    cudaGetSymbolAddress((void**)&wl,   g_wl);
    cudaGetSymbolAddress((void**)&ktok, g_ktok);
    cudaGetSymbolAddress((void**)&kw,   g_kw);
    cudaGetSymbolAddress((void**)&mk,   g_mk);
    cudaGetSymbolAddress((void**)&pos,  g_pos);

    PrepArgs pa;
    pa.x = x; pa.gw = gw; pa.gb = gb;
    pa.ew1 = ew1; pa.ew3 = ew3; pa.ew2 = ew2; pa.sw2 = sw2;
    pa.wg = wg; pa.w2h = w2h; pa.sw2h = sw2h;
    pa.topi = topi; pa.wts = wts;
    PrepArgs pz = {};

    cudaFuncSetAttribute((const void*)gemm_h<5,false,true>,  cudaFuncAttributeMaxDynamicSharedMemorySize, SMEM_BYTES);
    cudaFuncSetAttribute((const void*)gemm_h<3,false,false>, cudaFuncAttributeMaxDynamicSharedMemorySize, SMEM_BYTES);
    cudaFuncSetAttribute((const void*)gemm_dual,             cudaFuncAttributeMaxDynamicSharedMemorySize, SMEM_BYTES);

    // 0: consolidated front-end (hx convert, swg interleave, pos/cnt/mk init)
    prep0_kernel<<<20513, 256>>>(x, hx, sw1, sw3, swg, pos, cnt, mk);

    // 1: FAT shared fused-up GEMM (z=0,1) + prep slice (z=2): gate (16 tok/block),
    //    interleave wg, tohalf w2h, tohalf sw2h — hidden under tensor-bound GEMM work.
    gemm_h<5,false,true><<<dim3(2*HDIM/BN, NTOK/BM, 3), 256, SMEM_BYTES>>>(
        hx, 0, DDIM, swg, (size_t)DDIM*2*HDIM, act, (size_t)HDIM, 2*HDIM,
        nullptr, NTOK, 2*HDIM, DDIM, nullptr, nullptr, 1.f, 2, pa);

    // 2: expert membership lists (needs gate output)
    assign_kernel<<<(NTOK * 2 + 255) / 256, 256>>>(topi, wts, cnt, tokl, wl);

    // 3: capacity selection
    select_kernel<<<NEXP, 256>>>(cnt, tokl, wl, topi, ktok, kw, mk, pos);

    // 4: FUSED middle launch — shared-down (long-K tiles first, z=0,1) + routed-up
    gemm_dual<<<dim3(2*HDIM/BN, CAP/BM, NEXP + 2), 256, SMEM_BYTES>>>(
        hx, wg, act2, mk, ktok, act, sw2h, out);

    // 5: routed down-proj into y staging
    gemm_h<3,false,false><<<dim3(DDIM/BN, CAP/BM, NEXP), 256, SMEM_BYTES>>>(
        act2, (size_t)CAP*HDIM, HDIM, w2h, (size_t)HDIM*DDIM, yb, (size_t)CAP*DDIM, DDIM,
        mk, CAP, DDIM, HDIM, nullptr, kw, 1.f, -1, pz);

    // 6: final gather-sum (no atomics)
    combine_kernel<<<NTOK * 256 / 256, 256>>>(pos, yb, out);
}